// round 7
// baseline (speedup 1.0000x reference)
#include <cuda_runtime.h>
#include <cuda_bf16.h>
#include <cuda_fp16.h>
#include <cstdint>

// Problem constants
#define BB   2
#define CH   128
#define HWN  4096
#define NTOK 4096
#define BNC  8192          // BB * NTOK
#define CC   256           // 2*CH (real plane then imag plane)
#define NN   (4096ull*4096ull)
#define EPSV 1e-5f
#define SCALE_QK 0.08838834764831845f   // 1/sqrt(128)

typedef __nv_bfloat16 bf16;

// ---------------- scratch (device globals) ---------------------------------
__device__ __align__(256) float  g_x   [(size_t)CC * BNC];   // normalized planar fp32 (2C, B*N)
__device__ __align__(256) bf16   g_xt  [(size_t)BNC * CC];   // normalized token-major bf16
__device__ __align__(256) bf16   g_qt  [(size_t)BNC * CC];   // Q token-major bf16 (pre-scaled)
__device__ __align__(256) bf16   g_kt  [(size_t)BNC * CC];   // K token-major bf16
__device__ __align__(256) bf16   g_vp  [(size_t)CC * BNC];   // V planar bf16 (cc, B*N)
__device__ __align__(256) __half g_attn[(size_t)BB * NN];    // logits fp16 / attn bf16 in-place
__device__ __align__(256) float  g_o   [(size_t)BB * NTOK * CC]; // partial out, K-half 0
__device__ __align__(256) float  g_o2  [(size_t)BB * NTOK * CC]; // partial out, K-half 1
__device__ __align__(256) bf16   g_ws_bf[3 * CC * CC];       // stacked complex weights bf16
__device__ float g_bs  [3 * CC];
__device__ float g_scale[CC];
__device__ float g_shift[CC];

// ---------------- PTX helpers (base-ISA only) --------------------------------
__device__ __forceinline__ uint32_t smem_u32(const void* p) {
    uint32_t a;
    asm("{ .reg .u64 t; cvta.to.shared.u64 t, %1; cvt.u32.u64 %0, t; }" : "=r"(a) : "l"(p));
    return a;
}
__device__ __forceinline__ void cpa16(uint32_t dst, const void* src) {
    asm volatile("cp.async.cg.shared.global [%0], [%1], 16;" :: "r"(dst), "l"(src) : "memory");
}
#define CP_COMMIT() asm volatile("cp.async.commit_group;" ::: "memory")
#define CP_WAIT(n)  asm volatile("cp.async.wait_group %0;" :: "n"(n) : "memory")

#define LDMX4(r, addr) \
    asm volatile("ldmatrix.sync.aligned.m8n8.x4.shared.b16 {%0,%1,%2,%3}, [%4];" \
        : "=r"((r)[0]), "=r"((r)[1]), "=r"((r)[2]), "=r"((r)[3]) : "r"(addr))

#define MMA16816(d, a, b0v, b1v) \
    asm volatile("mma.sync.aligned.m16n8k16.row.col.f32.bf16.bf16.f32 " \
        "{%0,%1,%2,%3}, {%4,%5,%6,%7}, {%8,%9}, {%0,%1,%2,%3};" \
        : "+f"((d)[0]), "+f"((d)[1]), "+f"((d)[2]), "+f"((d)[3]) \
        : "r"((a)[0]), "r"((a)[1]), "r"((a)[2]), "r"((a)[3]), "r"(b0v), "r"(b1v))

// SMEM tile geometry: rows x 64 bf16 (128B data) padded to 144B/row.
#define ROWB    144
#define ATILEB  (128 * ROWB)         // 18432 B  (A: 128 rows)
#define BTILEB  (64 * ROWB)          //  9216 B  (B: 64 rows)
#define STAGES  2
#define SM_TOTAL (STAGES * (ATILEB + BTILEB))   // 55296 B

// ---------------- unified HMMA GEMM: D(128x64) = A(128xK) . B(64xK)^T -------
// EPI 0: proj  (grid 64 x 12)         A=g_xt,      B=g_ws_bf,  K=256
// EPI 1: logit (grid 32 x 64 x 2)     A=g_qt,      B=g_kt,     K=256  (fp16 out)
// EPI 2: out   (grid 32 x 4 x 4)      A=attn bf16, B=g_vp,     K=2048 (split-K=2)
template <int EPI>
__global__ __launch_bounds__(256, 3) void gemm_kernel() {
    extern __shared__ __align__(16) char smem[];
    const int tid = threadIdx.x, lane = tid & 31, wid = tid >> 5;
    const int bx = blockIdx.x, by = blockIdx.y, bz = blockIdx.z;

    const bf16 *Ap, *Bp; size_t lda, ldb; int nk;
    if (EPI == 0) {
        Ap = g_xt + (size_t)bx * 128 * CC;                 lda = CC;
        Bp = g_ws_bf + (size_t)by * 64 * CC;               ldb = CC;   nk = 4;
    } else if (EPI == 1) {
        Ap = g_qt + ((size_t)bz * NTOK + bx * 128) * CC;   lda = CC;
        Bp = g_kt + ((size_t)bz * NTOK + by * 64) * CC;    ldb = CC;   nk = 4;
    } else {
        const int b = bz >> 1, ks = bz & 1;
        Ap = (const bf16*)g_attn + ((size_t)b * NTOK + bx * 128) * NTOK + ks * 2048;
        lda = NTOK;
        Bp = g_vp + (size_t)(by * 64) * BNC + (size_t)b * NTOK + ks * 2048;
        ldb = BNC;  nk = 32;
    }

    const uint32_t sa0 = smem_u32(smem);                 // A stages: 2 x 18432
    const uint32_t sb0 = sa0 + STAGES * ATILEB;          // B stages: 2 x 9216

    auto load_tile = [&](int i) {
        const int kk0 = i * 64;
        const int st = i & 1;
        const uint32_t ab = sa0 + st * ATILEB;
        const uint32_t bb = sb0 + st * BTILEB;
        #pragma unroll
        for (int it = 0; it < 4; it++) {                 // A: 1024 chunks of 16B
            int l = tid + it * 256;
            int row = l >> 3, kc = l & 7;
            cpa16(ab + row * ROWB + kc * 16, Ap + (size_t)row * lda + kk0 + kc * 8);
        }
        #pragma unroll
        for (int it = 0; it < 2; it++) {                 // B: 512 chunks of 16B
            int l = tid + it * 256;
            int row = l >> 3, kc = l & 7;
            cpa16(bb + row * ROWB + kc * 16, Bp + (size_t)row * ldb + kk0 + kc * 8);
        }
    };

    float acc[2][4][4];
    #pragma unroll
    for (int mt = 0; mt < 2; mt++)
        #pragma unroll
        for (int nj = 0; nj < 4; nj++)
            #pragma unroll
            for (int e = 0; e < 4; e++) acc[mt][nj][e] = 0.f;

    const int m0  = (wid & 3) * 32;     // 4 warps along M (32 rows each)
    const int n0w = (wid >> 2) * 32;    // 2 warps along N (32 cols each)

    load_tile(0); CP_COMMIT();

    for (int i = 0; i < nk; i++) {
        if (i + 1 < nk) { load_tile(i + 1); CP_COMMIT(); CP_WAIT(1); }
        else            { CP_WAIT(0); }
        __syncthreads();

        const int st = i & 1;
        const uint32_t aB = sa0 + st * ATILEB;
        const uint32_t bB = sb0 + st * BTILEB;
        #pragma unroll
        for (int ks = 0; ks < 64; ks += 16) {
            uint32_t af[2][4], bfr[2][4];
            #pragma unroll
            for (int mt = 0; mt < 2; mt++) {
                uint32_t addr = aB + (m0 + mt * 16 + (lane & 15)) * ROWB
                              + (ks + ((lane >> 4) << 3)) * 2;
                LDMX4(af[mt], addr);
            }
            #pragma unroll
            for (int nt = 0; nt < 2; nt++) {
                uint32_t addr = bB + (n0w + nt * 16 + (lane & 7) + ((lane & 16) >> 1)) * ROWB
                              + (ks + (((lane >> 3) & 1) << 3)) * 2;
                LDMX4(bfr[nt], addr);
            }
            #pragma unroll
            for (int mt = 0; mt < 2; mt++)
                #pragma unroll
                for (int nt = 0; nt < 2; nt++) {
                    MMA16816(acc[mt][2 * nt],     af[mt], bfr[nt][0], bfr[nt][1]);
                    MMA16816(acc[mt][2 * nt + 1], af[mt], bfr[nt][2], bfr[nt][3]);
                }
        }
        __syncthreads();
    }

    // ---- epilogue ----
    const int r_base = bx * 128 + m0 + (lane >> 2);
    const int c_loc0 = n0w + (lane & 3) * 2;

    #pragma unroll
    for (int mt = 0; mt < 2; mt++) {
        #pragma unroll
        for (int nj = 0; nj < 4; nj++) {
            float* d = acc[mt][nj];
            const int r0 = r_base + mt * 16;
            const int c  = c_loc0 + nj * 8;           // local N col 0..63

            if (EPI == 0) {
                int gc = by * 64 + c;                 // stacked output channel 0..767
                float bi0 = g_bs[gc], bi1 = g_bs[gc + 1];
                if (gc < 256) {                       // Q: pre-scale by SCALE_QK
                    __nv_bfloat162 v0 = __float22bfloat162_rn(
                        make_float2((d[0] + bi0) * SCALE_QK, (d[1] + bi1) * SCALE_QK));
                    __nv_bfloat162 v1 = __float22bfloat162_rn(
                        make_float2((d[2] + bi0) * SCALE_QK, (d[3] + bi1) * SCALE_QK));
                    *(__nv_bfloat162*)&g_qt[(size_t)r0 * CC + gc]       = v0;
                    *(__nv_bfloat162*)&g_qt[(size_t)(r0 + 8) * CC + gc] = v1;
                } else if (gc < 512) {                // K
                    int cc = gc - 256;
                    __nv_bfloat162 v0 = __float22bfloat162_rn(make_float2(d[0] + bi0, d[1] + bi1));
                    __nv_bfloat162 v1 = __float22bfloat162_rn(make_float2(d[2] + bi0, d[3] + bi1));
                    *(__nv_bfloat162*)&g_kt[(size_t)r0 * CC + cc]       = v0;
                    *(__nv_bfloat162*)&g_kt[(size_t)(r0 + 8) * CC + cc] = v1;
                } else {                              // V: planar
                    int cc = gc - 512;
                    g_vp[(size_t)cc * BNC + r0]           = __float2bfloat16(d[0] + bi0);
                    g_vp[(size_t)(cc + 1) * BNC + r0]     = __float2bfloat16(d[1] + bi1);
                    g_vp[(size_t)cc * BNC + r0 + 8]       = __float2bfloat16(d[2] + bi0);
                    g_vp[(size_t)(cc + 1) * BNC + r0 + 8] = __float2bfloat16(d[3] + bi1);
                }
            } else if (EPI == 1) {
                __half* L = g_attn + (size_t)bz * NN;     // scale folded into Q
                size_t col = (size_t)by * 64 + c;
                __half2 v0 = __floats2half2_rn(d[0], d[1]);
                __half2 v1 = __floats2half2_rn(d[2], d[3]);
                *(__half2*)&L[(size_t)r0 * NTOK + col]       = v0;
                *(__half2*)&L[(size_t)(r0 + 8) * NTOK + col] = v1;
            } else {
                const int b = bz >> 1, ks = bz & 1;
                int cc = by * 64 + c;
                float* O = (ks ? g_o2 : g_o) + (size_t)b * NTOK * CC;
                *(float2*)&O[(size_t)r0 * CC + cc]       = make_float2(d[0], d[1]);
                *(float2*)&O[(size_t)(r0 + 8) * CC + cc] = make_float2(d[2], d[3]);
            }
        }
    }
}

// ---------------- BN statistics: one block per channel, float4 loads -------
__global__ __launch_bounds__(256) void bn_stats_kernel(const float* __restrict__ x,
                                const float* __restrict__ bn_w,
                                const float* __restrict__ bn_b) {
    int c = blockIdx.x;
    float sr = 0.f, si = 0.f, qr = 0.f, qi = 0.f;
    #pragma unroll
    for (int b = 0; b < BB; b++) {
        const float4* p = (const float4*)x + (size_t)(b * CH + c) * (HWN / 2);
        for (int i = threadIdx.x; i < HWN / 2; i += 256) {
            float4 v = p[i];
            sr += v.x + v.z;  si += v.y + v.w;
            qr += v.x * v.x + v.z * v.z;
            qi += v.y * v.y + v.w * v.w;
        }
    }
    #pragma unroll
    for (int o = 16; o > 0; o >>= 1) {
        sr += __shfl_xor_sync(0xFFFFFFFF, sr, o);
        si += __shfl_xor_sync(0xFFFFFFFF, si, o);
        qr += __shfl_xor_sync(0xFFFFFFFF, qr, o);
        qi += __shfl_xor_sync(0xFFFFFFFF, qi, o);
    }
    __shared__ float s4[4][8];
    int wid = threadIdx.x >> 5, lane = threadIdx.x & 31;
    if (lane == 0) { s4[0][wid] = sr; s4[1][wid] = si; s4[2][wid] = qr; s4[3][wid] = qi; }
    __syncthreads();
    if (threadIdx.x == 0) {
        float tsr = 0, tsi = 0, tqr = 0, tqi = 0;
        #pragma unroll
        for (int w = 0; w < 8; w++) { tsr += s4[0][w]; tsi += s4[1][w]; tqr += s4[2][w]; tqi += s4[3][w]; }
        const float inv = 1.f / (float)(BB * HWN);
        float mr = tsr * inv, mi = tsi * inv;
        float vr = tqr * inv - mr * mr, vi = tqi * inv - mi * mi;
        float scr = bn_w[c * 2 + 0] * rsqrtf(vr + EPSV);
        float sci = bn_w[c * 2 + 1] * rsqrtf(vi + EPSV);
        g_scale[c]      = scr;  g_shift[c]      = bn_b[c * 2 + 0] - mr * scr;
        g_scale[CH + c] = sci;  g_shift[CH + c] = bn_b[c * 2 + 1] - mi * sci;
    }
}

// ---------------- normalize: planar fp32 + token-major bf16 -----------------
__global__ void normalize_kernel(const float* __restrict__ x) {
    __shared__ float shr[32][33];
    __shared__ float shi[32][33];
    int b  = blockIdx.z;
    int c0 = blockIdx.y * 32;
    int n0 = blockIdx.x * 32;
    int tx = threadIdx.x, ty = threadIdx.y;
    int c = c0 + ty, n = n0 + tx;
    float2 v = ((const float2*)x)[(size_t)(b * CH + c) * HWN + n];
    float xr = v.x * g_scale[c]      + g_shift[c];
    float xi = v.y * g_scale[CH + c] + g_shift[CH + c];
    size_t col = (size_t)b * NTOK + n;
    g_x[(size_t)c * BNC + col]        = xr;
    g_x[(size_t)(CH + c) * BNC + col] = xi;
    shr[ty][tx] = xr; shi[ty][tx] = xi;
    __syncthreads();
    int token = n0 + ty, cw = c0 + tx;
    bf16* dst = g_xt + ((size_t)b * NTOK + token) * CC;
    dst[cw]      = __float2bfloat16(shr[tx][ty]);
    dst[CH + cw] = __float2bfloat16(shi[tx][ty]);
}

// ---------------- stacked complex weights (bf16) ----------------------------
__global__ void stack_w_kernel(const float* __restrict__ wq, const float* __restrict__ bq,
                               const float* __restrict__ wk, const float* __restrict__ bk,
                               const float* __restrict__ wv, const float* __restrict__ bv) {
    int idx = blockIdx.x * blockDim.x + threadIdx.x;
    if (idx >= 3 * CH * CH) return;
    int p = idx / (CH * CH);
    int r = idx - p * (CH * CH);
    int o = r / CH, i = r % CH;
    const float* w = (p == 0) ? wq : ((p == 1) ? wk : wv);
    float wr = w[(o * CH + i) * 2 + 0];
    float wi = w[(o * CH + i) * 2 + 1];
    bf16* ws = g_ws_bf + (size_t)p * CC * CC;
    ws[o * CC + i]             = __float2bfloat16( wr);
    ws[o * CC + CH + i]        = __float2bfloat16(-wi);
    ws[(CH + o) * CC + i]      = __float2bfloat16( wi);
    ws[(CH + o) * CC + CH + i] = __float2bfloat16( wr);
    if (i == 0) {
        const float* bbp = (p == 0) ? bq : ((p == 1) ? bk : bv);
        g_bs[p * CC + o]      = bbp[o * 2 + 0];
        g_bs[p * CC + CH + o] = bbp[o * 2 + 1];
    }
}

// ---------------- softmax (fp16 in, bf16 out in place, shuffle reductions) --
__global__ __launch_bounds__(256) void softmax_kernel() {
    size_t rid = blockIdx.x;
    __half2* row2 = (__half2*)(g_attn + rid * NTOK);
    int t = threadIdx.x, wid = t >> 5, lane = t & 31;
    __shared__ float sw[8];

    float2 v[8];
    float mx = -1e30f;
    #pragma unroll
    for (int k = 0; k < 8; k++) {
        v[k] = __half22float2(row2[t + k * 256]);
        mx = fmaxf(mx, fmaxf(v[k].x, v[k].y));
    }
    #pragma unroll
    for (int o = 16; o > 0; o >>= 1) mx = fmaxf(mx, __shfl_xor_sync(0xFFFFFFFF, mx, o));
    if (lane == 0) sw[wid] = mx;
    __syncthreads();
    mx = sw[lane & 7];
    #pragma unroll
    for (int o = 4; o > 0; o >>= 1) mx = fmaxf(mx, __shfl_xor_sync(0xFFFFFFFF, mx, o));

    float sum = 0.f;
    #pragma unroll
    for (int k = 0; k < 8; k++) {
        v[k].x = __expf(v[k].x - mx); v[k].y = __expf(v[k].y - mx);
        sum += v[k].x + v[k].y;
    }
    #pragma unroll
    for (int o = 16; o > 0; o >>= 1) sum += __shfl_xor_sync(0xFFFFFFFF, sum, o);
    __syncthreads();
    if (lane == 0) sw[wid] = sum;
    __syncthreads();
    sum = sw[lane & 7];
    #pragma unroll
    for (int o = 4; o > 0; o >>= 1) sum += __shfl_xor_sync(0xFFFFFFFF, sum, o);

    float inv = 1.f / sum;
    __nv_bfloat162* brow = (__nv_bfloat162*)(g_attn + rid * NTOK);
    #pragma unroll
    for (int k = 0; k < 8; k++)
        brow[t + k * 256] = __float22bfloat162_rn(make_float2(v[k].x * inv, v[k].y * inv));
}

// ---------------- residual add (vs normalized xn) + combine split-K ---------
__global__ void final_add_kernel(const float* __restrict__ gamma_p,
                                 float* __restrict__ out) {
    __shared__ float shr[32][33];
    __shared__ float shi[32][33];
    float gamma = *gamma_p;
    int b  = blockIdx.z;
    int c0 = blockIdx.y * 32;
    int n0 = blockIdx.x * 32;
    int tx = threadIdx.x, ty = threadIdx.y;
    size_t obase = ((size_t)b * NTOK + n0 + ty) * CC;
    shr[ty][tx] = g_o[obase + c0 + tx]      + g_o2[obase + c0 + tx];
    shi[ty][tx] = g_o[obase + CH + c0 + tx] + g_o2[obase + CH + c0 + tx];
    __syncthreads();
    int c = c0 + ty;
    int n = n0 + tx;
    size_t col = (size_t)b * NTOK + n;
    float xr = g_x[(size_t)c * BNC + col];
    float xi = g_x[(size_t)(CH + c) * BNC + col];
    size_t oi = (size_t)(b * CH + c) * HWN + n;
    float2 ov;
    ov.x = xr + gamma * shr[tx][ty];
    ov.y = xi + gamma * shi[tx][ty];
    ((float2*)out)[oi] = ov;
}

// ---------------- launch -----------------------------------------------------
extern "C" void kernel_launch(void* const* d_in, const int* in_sizes, int n_in,
                              void* d_out, int out_size) {
    const float* x    = (const float*)d_in[0];
    const float* bn_w = (const float*)d_in[1];
    const float* bn_b = (const float*)d_in[2];
    const float* wq   = (const float*)d_in[3];
    const float* bq   = (const float*)d_in[4];
    const float* wk   = (const float*)d_in[5];
    const float* bk   = (const float*)d_in[6];
    const float* wv   = (const float*)d_in[7];
    const float* bv   = (const float*)d_in[8];
    const float* gam  = (const float*)d_in[9];
    float* out = (float*)d_out;

    static int attr_set = 0;
    if (!attr_set) {
        cudaFuncSetAttribute(gemm_kernel<0>, cudaFuncAttributeMaxDynamicSharedMemorySize, SM_TOTAL);
        cudaFuncSetAttribute(gemm_kernel<1>, cudaFuncAttributeMaxDynamicSharedMemorySize, SM_TOTAL);
        cudaFuncSetAttribute(gemm_kernel<2>, cudaFuncAttributeMaxDynamicSharedMemorySize, SM_TOTAL);
        attr_set = 1;
    }

    bn_stats_kernel<<<CH, 256>>>(x, bn_w, bn_b);
    normalize_kernel<<<dim3(HWN / 32, CH / 32, BB), dim3(32, 32)>>>(x);
    stack_w_kernel<<<(3 * CH * CH + 255) / 256, 256>>>(wq, bq, wk, bk, wv, bv);
    gemm_kernel<0><<<dim3(BNC / 128, 12), 256, SM_TOTAL>>>();
    gemm_kernel<1><<<dim3(NTOK / 128, NTOK / 64, BB), 256, SM_TOTAL>>>();
    softmax_kernel<<<BB * NTOK, 256>>>();
    gemm_kernel<2><<<dim3(NTOK / 128, CC / 64, BB * 2), 256, SM_TOTAL>>>();
    final_add_kernel<<<dim3(HWN / 32, CH / 32, BB), dim3(32, 32)>>>(gam, out);
}